// round 2
// baseline (speedup 1.0000x reference)
#include <cuda_runtime.h>
#include <math.h>

#define NT 128

// shared-memory weight bank offsets (cumulative)
#define C1W 0
#define C1B 216
#define C2W 222
#define C2B 294
#define C3W 298
#define C3B 346
#define E1W 350
#define E1B 374
#define E2W 378
#define E2B 394
#define D1W 398
#define D1B 446
#define D2W 450
#define D2B 474
#define D3W 476
#define D3B 488
#define D4W 490
#define D4B 742
#define WTOT 748

__global__ __launch_bounds__(NT, 1)
void conv_policy_kernel(const float* __restrict__ x,
                        const float* __restrict__ c1w, const float* __restrict__ c1b,
                        const float* __restrict__ c2w, const float* __restrict__ c2b,
                        const float* __restrict__ c3w, const float* __restrict__ c3b,
                        const float* __restrict__ e1w, const float* __restrict__ e1b,
                        const float* __restrict__ e2w, const float* __restrict__ e2b,
                        const float* __restrict__ d1w, const float* __restrict__ d1b,
                        const float* __restrict__ d2w, const float* __restrict__ d2b,
                        const float* __restrict__ d3w, const float* __restrict__ d3b,
                        const float* __restrict__ d4w, const float* __restrict__ d4b,
                        float* __restrict__ out)
{
    __shared__ float W[WTOT];
    __shared__ float jcat[12][15];
    __shared__ float fm1[6][13];
    __shared__ float fm1ds[6][5];
    __shared__ float fm2[4][3];
    __shared__ float embin[6];
    __shared__ float emb1s[4];
    __shared__ float emb2s[4];
    __shared__ float dc1[4][3];
    __shared__ float dc2[2][5];
    __shared__ float dc3[2][15];

    const int t = threadIdx.x;

    // ---- phase 0: prefetch ALL weights into smem (one parallel LDG batch),
    //      build jcat, compute psi — all independent, one barrier total.
    #define CP(off, src, n) for (int i = t; i < (n); i += NT) W[(off) + i] = (src)[i];
    CP(C1W, c1w, 216) CP(C1B, c1b, 6)
    CP(C2W, c2w, 72)  CP(C2B, c2b, 4)
    CP(C3W, c3w, 48)  CP(C3B, c3b, 4)
    CP(E1W, e1w, 24)  CP(E1B, e1b, 4)
    CP(E2W, e2w, 16)  CP(E2B, e2b, 4)
    CP(D1W, d1w, 48)  CP(D1B, d1b, 4)
    CP(D2W, d2w, 24)  CP(D2B, d2b, 2)
    CP(D3W, d3w, 12)  CP(D3B, d3b, 2)
    CP(D4W, d4w, 252) CP(D4B, d4b, 6)
    #undef CP

    for (int idx = t; idx < 180; idx += NT) {
        int c = idx / 15, l = idx % 15;
        float v;
        if (c < 6) {
            int j = c * 15 + l;
            v = (j < 2) ? 0.0f : x[7 + j - 2];
        } else {
            int j = (c - 6) * 15 + l;
            v = (j < 2) ? 0.0f : x[101 + j - 2];
        }
        jcat[c][l] = v;
    }
    if (t == 96) {  // psi + obsd tail, off the critical chain
        float qw = x[3], qx = x[4], qy = x[5], qz = x[6];
        embin[4] = atan2f(qz, qw) - atan2f(-qx, qy);
        embin[5] = x[100];
    }
    __syncthreads();

    // ---- conv1: (12,15) k=3 -> (6,13), tanh   [78 threads, warps 0-2]
    if (t < 78) {
        int o = t / 13, l = t % 13;
        float s = W[C1B + o];
        #pragma unroll
        for (int i = 0; i < 12; i++)
            #pragma unroll
            for (int h = 0; h < 3; h++)
                s = fmaf(W[C1W + (o * 12 + i) * 3 + h], jcat[i][l + h], s);
        fm1[o][l] = tanhf(s);
    }
    __syncthreads();

    // ---- middle section: all stages fit in warp 0, syncwarp only ----
    if (t < 32) {
        // adaptive avg pool 13 -> 5  [30 lanes]
        if (t < 30) {
            const int S[5] = {0, 2, 5, 7, 10};
            const int E[5] = {3, 6, 8, 11, 13};
            int o = t / 5, p = t % 5;
            float s = 0.0f;
            for (int l = S[p]; l < E[p]; l++) s += fm1[o][l];
            fm1ds[o][p] = s / (float)(E[p] - S[p]);
        }
        __syncwarp();

        // conv2: (6,5) k=3 -> (4,3), tanh  [12 lanes]
        if (t < 12) {
            int o = t / 3, l = t % 3;
            float s = W[C2B + o];
            #pragma unroll
            for (int i = 0; i < 6; i++)
                #pragma unroll
                for (int h = 0; h < 3; h++)
                    s = fmaf(W[C2W + (o * 6 + i) * 3 + h], fm1ds[i][l + h], s);
            fm2[o][l] = tanhf(s);
        }
        __syncwarp();

        // conv3: (4,3) k=3 -> (4,1), tanh; mean over len-1 is identity  [4 lanes]
        if (t < 4) {
            float s = W[C3B + t];
            #pragma unroll
            for (int i = 0; i < 4; i++)
                #pragma unroll
                for (int h = 0; h < 3; h++)
                    s = fmaf(W[C3W + (t * 4 + i) * 3 + h], fm2[i][h], s);
            embin[t] = tanhf(s);
        }
        __syncwarp();

        // emb1: 1x1 conv 6->4, tanh  [4 lanes]
        if (t < 4) {
            float s = W[E1B + t];
            #pragma unroll
            for (int i = 0; i < 6; i++) s = fmaf(W[E1W + t * 6 + i], embin[i], s);
            emb1s[t] = tanhf(s);
        }
        __syncwarp();

        // emb2: 1x1 conv 4->4, tanh  [4 lanes]
        if (t < 4) {
            float s = W[E2B + t];
            #pragma unroll
            for (int i = 0; i < 4; i++) s = fmaf(W[E2W + t * 4 + i], emb1s[i], s);
            emb2s[t] = tanhf(s);
        }
        __syncwarp();

        // dec1: convT 4->4 k=3, len 1 -> 3, tanh  [12 lanes]
        if (t < 12) {
            int o = t / 3, l = t % 3;
            float s = W[D1B + o];
            #pragma unroll
            for (int i = 0; i < 4; i++)
                s = fmaf(W[D1W + (i * 4 + o) * 3 + l], emb2s[i], s);
            dc1[o][l] = tanhf(s);
        }
        __syncwarp();

        // dec2: convT 4->2 k=3, len 3 -> 5, tanh  [10 lanes]
        if (t < 10) {
            int o = t / 5, l = t % 5;
            float s = W[D2B + o];
            #pragma unroll
            for (int i = 0; i < 4; i++)
                #pragma unroll
                for (int h = 0; h < 3; h++) {
                    int p = l - h;
                    if (p >= 0 && p < 3)
                        s = fmaf(W[D2W + (i * 2 + o) * 3 + h], dc1[i][p], s);
                }
            dc2[o][l] = tanhf(s);
        }
        __syncwarp();

        // dec3 with fused index-upsample: convT 2->2 k=3, len 13 -> 15, tanh  [30 lanes]
        if (t < 30) {
            const int UP[13] = {0, 0, 0, 1, 1, 1, 2, 2, 3, 3, 3, 4, 4};
            int o = t / 15, l = t % 15;
            float s = W[D3B + o];
            #pragma unroll
            for (int i = 0; i < 2; i++)
                #pragma unroll
                for (int h = 0; h < 3; h++) {
                    int p = l - h;
                    if (p >= 0 && p < 13)
                        s = fmaf(W[D3W + (i * 2 + o) * 3 + h], dc2[i][UP[p]], s);
                }
            dc3[o][l] = tanhf(s);
        }
    }
    __syncthreads();

    // ---- dec4: convT 14->6 k=3 pad=1, (14,15) -> (6,15); drop first 2 -> 88  [88 threads]
    if (t < 88) {
        int g = t + 2;
        int o = g / 15, l = g % 15;
        float s = W[D4B + o];
        #pragma unroll
        for (int h = 0; h < 3; h++) {
            int p = l - h + 1;
            if (p >= 0 && p < 15) {
                #pragma unroll
                for (int i = 0; i < 14; i++) {
                    float v = (i < 2) ? dc3[i][p] : jcat[i - 2][p];
                    s = fmaf(W[D4W + (i * 6 + o) * 3 + h], v, s);
                }
            }
        }
        out[t] = s;
    }
}

extern "C" void kernel_launch(void* const* d_in, const int* in_sizes, int n_in,
                              void* d_out, int out_size) {
    (void)in_sizes; (void)n_in; (void)out_size;
    conv_policy_kernel<<<1, NT>>>(
        (const float*)d_in[0],
        (const float*)d_in[1],  (const float*)d_in[2],
        (const float*)d_in[3],  (const float*)d_in[4],
        (const float*)d_in[5],  (const float*)d_in[6],
        (const float*)d_in[7],  (const float*)d_in[8],
        (const float*)d_in[9],  (const float*)d_in[10],
        (const float*)d_in[11], (const float*)d_in[12],
        (const float*)d_in[13], (const float*)d_in[14],
        (const float*)d_in[15], (const float*)d_in[16],
        (const float*)d_in[17], (const float*)d_in[18],
        (float*)d_out);
}

// round 3
// speedup vs baseline: 1.7824x; 1.7824x over previous
#include <cuda_runtime.h>
#include <math.h>

#define NT 96

// shared weight bank (middle stages only)
#define C2W 0
#define C2B 72
#define C3W 76
#define C3B 124
#define E1W 128
#define E1B 152
#define E2W 156
#define E2B 172
#define D1W 176
#define D1B 224
#define D2W 228
#define D2B 252
#define D3W 254
#define D3B 266
#define WTOT 268

__device__ __forceinline__ float htanh(float x) {
    float y;
    asm("tanh.approx.f32 %0, %1;" : "=f"(y) : "f"(x));
    return y;
}

__global__ __launch_bounds__(NT, 1)
void conv_policy_kernel(const float* __restrict__ x,
                        const float* __restrict__ c1w, const float* __restrict__ c1b,
                        const float* __restrict__ c2w, const float* __restrict__ c2b,
                        const float* __restrict__ c3w, const float* __restrict__ c3b,
                        const float* __restrict__ e1w, const float* __restrict__ e1b,
                        const float* __restrict__ e2w, const float* __restrict__ e2b,
                        const float* __restrict__ d1w, const float* __restrict__ d1b,
                        const float* __restrict__ d2w, const float* __restrict__ d2b,
                        const float* __restrict__ d3w, const float* __restrict__ d3b,
                        const float* __restrict__ d4w, const float* __restrict__ d4b,
                        float* __restrict__ out)
{
    __shared__ float W[WTOT];
    __shared__ float cat[14][15];    // rows 0-1: dc3 (filled late); rows 2-13: jcat
    __shared__ float fm1[6][13];
    __shared__ float fm1ds[6][5];
    __shared__ float fm2[4][3];
    __shared__ float embin[6];
    __shared__ float emb1s[4];
    __shared__ float emb2s[4];
    __shared__ float dc1[4][3];
    __shared__ float dc2[2][5];

    const int t = threadIdx.x;

    // ================= phase 0: everything independent, one barrier =========
    // per-thread register preload of conv1 weights (threads 0..77)
    float w1[36], b1 = 0.0f;
    int o1 = 0, l1 = 0;
    if (t < 78) {
        o1 = t / 13; l1 = t % 13;
        #pragma unroll
        for (int i = 0; i < 36; i++) w1[i] = c1w[o1 * 36 + i];
        b1 = c1b[o1];
    }
    // per-thread register preload of dec4 weights (threads 0..87)
    float w4[42], b4 = 0.0f;
    int o4 = 0, l4 = 0;
    if (t < 88) {
        int g = t + 2; o4 = g / 15; l4 = g % 15;
        #pragma unroll
        for (int i = 0; i < 14; i++)
            #pragma unroll
            for (int h = 0; h < 3; h++)
                w4[i * 3 + h] = d4w[i * 18 + o4 * 3 + h];
        b4 = d4b[o4];
    }
    // middle-stage weights -> shared bank
    #define CP(off, src, n) for (int i = t; i < (n); i += NT) W[(off) + i] = (src)[i];
    CP(C2W, c2w, 72)  CP(C2B, c2b, 4)
    CP(C3W, c3w, 48)  CP(C3B, c3b, 4)
    CP(E1W, e1w, 24)  CP(E1B, e1b, 4)
    CP(E2W, e2w, 16)  CP(E2B, e2b, 4)
    CP(D1W, d1w, 48)  CP(D1B, d1b, 4)
    CP(D2W, d2w, 24)  CP(D2B, d2b, 2)
    CP(D3W, d3w, 12)  CP(D3B, d3b, 2)
    #undef CP
    // jcat -> cat rows 2..13
    for (int idx = t; idx < 180; idx += NT) {
        int c = idx / 15, l = idx % 15;
        float v;
        if (c < 6) {
            int j = c * 15 + l;
            v = (j < 2) ? 0.0f : x[7 + j - 2];
        } else {
            int j = (c - 6) * 15 + l;
            v = (j < 2) ? 0.0f : x[101 + j - 2];
        }
        cat[2 + c][l] = v;
    }
    if (t == 95) {  // psi + obsd tail, off the chain
        float qw = x[3], qx = x[4], qy = x[5], qz = x[6];
        embin[4] = atan2f(qz, qw) - atan2f(-qx, qy);
        embin[5] = x[100];
    }
    __syncthreads();

    // ================= conv1: (12,15) k=3 -> (6,13), tanh ===================
    if (t < 78) {
        float s0 = b1, s1 = 0.0f, s2 = 0.0f;
        #pragma unroll
        for (int i = 0; i < 12; i++) {
            s0 = fmaf(w1[i * 3 + 0], cat[2 + i][l1 + 0], s0);
            s1 = fmaf(w1[i * 3 + 1], cat[2 + i][l1 + 1], s1);
            s2 = fmaf(w1[i * 3 + 2], cat[2 + i][l1 + 2], s2);
        }
        fm1[o1][l1] = htanh(s0 + s1 + s2);
    }
    __syncthreads();

    // ================= middle: warp 0 only, syncwarp barriers ===============
    if (t < 32) {
        // adaptive avg pool 13 -> 5
        if (t < 30) {
            const int   S[5] = {0, 2, 5, 7, 10};
            const int   E[5] = {3, 6, 8, 11, 13};
            const float R[5] = {1.f/3.f, 0.25f, 1.f/3.f, 0.25f, 1.f/3.f};
            int o = t / 5, p = t % 5;
            float s = 0.0f;
            for (int l = S[p]; l < E[p]; l++) s += fm1[o][l];
            fm1ds[o][p] = s * R[p];
        }
        __syncwarp();

        // conv2: (6,5) k=3 -> (4,3), tanh
        if (t < 12) {
            int o = t / 3, l = t % 3;
            float s0 = W[C2B + o], s1 = 0.0f;
            #pragma unroll
            for (int i = 0; i < 6; i++) {
                s0 = fmaf(W[C2W + (o * 6 + i) * 3 + 0], fm1ds[i][l + 0], s0);
                s1 = fmaf(W[C2W + (o * 6 + i) * 3 + 1], fm1ds[i][l + 1], s1);
                s0 = fmaf(W[C2W + (o * 6 + i) * 3 + 2], fm1ds[i][l + 2], s0);
            }
            fm2[o][l] = htanh(s0 + s1);
        }
        __syncwarp();

        // conv3: (4,3) k=3 -> (4,1), tanh (mean over len 1 = identity)
        if (t < 4) {
            float s0 = W[C3B + t], s1 = 0.0f;
            #pragma unroll
            for (int i = 0; i < 4; i++) {
                s0 = fmaf(W[C3W + (t * 4 + i) * 3 + 0], fm2[i][0], s0);
                s1 = fmaf(W[C3W + (t * 4 + i) * 3 + 1], fm2[i][1], s1);
                s0 = fmaf(W[C3W + (t * 4 + i) * 3 + 2], fm2[i][2], s0);
            }
            embin[t] = htanh(s0 + s1);
        }
        __syncwarp();

        // emb1: 1x1, 6->4, tanh
        if (t < 4) {
            float s0 = W[E1B + t], s1 = 0.0f;
            #pragma unroll
            for (int i = 0; i < 6; i += 2) {
                s0 = fmaf(W[E1W + t * 6 + i], embin[i], s0);
                s1 = fmaf(W[E1W + t * 6 + i + 1], embin[i + 1], s1);
            }
            emb1s[t] = htanh(s0 + s1);
        }
        __syncwarp();

        // emb2: 1x1, 4->4, tanh
        if (t < 4) {
            float s0 = W[E2B + t], s1 = 0.0f;
            s0 = fmaf(W[E2W + t * 4 + 0], emb1s[0], s0);
            s1 = fmaf(W[E2W + t * 4 + 1], emb1s[1], s1);
            s0 = fmaf(W[E2W + t * 4 + 2], emb1s[2], s0);
            s1 = fmaf(W[E2W + t * 4 + 3], emb1s[3], s1);
            emb2s[t] = htanh(s0 + s1);
        }
        __syncwarp();

        // dec1: convT 4->4 k=3, len 1 -> 3, tanh
        if (t < 12) {
            int o = t / 3, l = t % 3;
            float s0 = W[D1B + o], s1 = 0.0f;
            s0 = fmaf(W[D1W + (0 * 4 + o) * 3 + l], emb2s[0], s0);
            s1 = fmaf(W[D1W + (1 * 4 + o) * 3 + l], emb2s[1], s1);
            s0 = fmaf(W[D1W + (2 * 4 + o) * 3 + l], emb2s[2], s0);
            s1 = fmaf(W[D1W + (3 * 4 + o) * 3 + l], emb2s[3], s1);
            dc1[o][l] = htanh(s0 + s1);
        }
        __syncwarp();

        // dec2: convT 4->2 k=3, len 3 -> 5, tanh
        if (t < 10) {
            int o = t / 5, l = t % 5;
            float s0 = W[D2B + o], s1 = 0.0f;
            #pragma unroll
            for (int i = 0; i < 4; i++)
                #pragma unroll
                for (int h = 0; h < 3; h++) {
                    int p = l - h;
                    if (p >= 0 && p < 3) {
                        if (h & 1) s1 = fmaf(W[D2W + (i * 2 + o) * 3 + h], dc1[i][p], s1);
                        else       s0 = fmaf(W[D2W + (i * 2 + o) * 3 + h], dc1[i][p], s0);
                    }
                }
            dc2[o][l] = htanh(s0 + s1);
        }
        __syncwarp();

        // dec3 + fused upsample: convT 2->2 k=3, len 13 -> 15, EXACT tanh
        // writes into cat rows 0..1 for dec4
        if (t < 30) {
            const int UP[13] = {0, 0, 0, 1, 1, 1, 2, 2, 3, 3, 3, 4, 4};
            int o = t / 15, l = t % 15;
            float s0 = W[D3B + o], s1 = 0.0f;
            #pragma unroll
            for (int i = 0; i < 2; i++)
                #pragma unroll
                for (int h = 0; h < 3; h++) {
                    int p = l - h;
                    if (p >= 0 && p < 13) {
                        if (h & 1) s1 = fmaf(W[D3W + (i * 2 + o) * 3 + h], dc2[i][UP[p]], s1);
                        else       s0 = fmaf(W[D3W + (i * 2 + o) * 3 + h], dc2[i][UP[p]], s0);
                    }
                }
            cat[o][l] = tanhf(s0 + s1);
        }
    }
    __syncthreads();

    // ================= dec4: convT 14->6 k=3 pad=1, (14,15)->(6,15), drop 2 =
    if (t < 88) {
        float s0 = b4, s1 = 0.0f, s2 = 0.0f;
        #pragma unroll
        for (int h = 0; h < 3; h++) {
            int p = l4 - h + 1;
            if (p >= 0 && p < 15) {
                #pragma unroll
                for (int i = 0; i < 14; i++) {
                    float v = cat[i][p];
                    if (i % 3 == 0)      s0 = fmaf(w4[i * 3 + h], v, s0);
                    else if (i % 3 == 1) s1 = fmaf(w4[i * 3 + h], v, s1);
                    else                 s2 = fmaf(w4[i * 3 + h], v, s2);
                }
            }
        }
        out[t] = s0 + s1 + s2;
    }
}

extern "C" void kernel_launch(void* const* d_in, const int* in_sizes, int n_in,
                              void* d_out, int out_size) {
    (void)in_sizes; (void)n_in; (void)out_size;
    conv_policy_kernel<<<1, NT>>>(
        (const float*)d_in[0],
        (const float*)d_in[1],  (const float*)d_in[2],
        (const float*)d_in[3],  (const float*)d_in[4],
        (const float*)d_in[5],  (const float*)d_in[6],
        (const float*)d_in[7],  (const float*)d_in[8],
        (const float*)d_in[9],  (const float*)d_in[10],
        (const float*)d_in[11], (const float*)d_in[12],
        (const float*)d_in[13], (const float*)d_in[14],
        (const float*)d_in[15], (const float*)d_in[16],
        (const float*)d_in[17], (const float*)d_in[18],
        (float*)d_out);
}